// round 1
// baseline (speedup 1.0000x reference)
#include <cuda_runtime.h>
#include <cstdint>

// Problem constants
#define B  8
#define HW 4096
#define HDIM 64
#define C  1024
#define M  32
#define P  512

#define NCHUNK 32
#define PIXPC  (HW / NCHUNK)   // 128 pixels per chunk
#define CPAIR  (C / 2)         // 512 float2 channel pairs

// Scratch: weights [B*M][HW] (4 MB) and partial sums [NCHUNK][B*M][CPAIR] float2 (32 MB)
__device__ float  g_W[(size_t)B * M * HW];
__device__ float2 g_partial[(size_t)NCHUNK * B * M * CPAIR];

// ---------------------------------------------------------------------------
// packed f32x2 helpers (sm_103a FFMA2 path — full-rate fp32)
// ---------------------------------------------------------------------------
__device__ __forceinline__ unsigned long long f2_as_u64(float x, float y) {
    unsigned long long r;
    asm("mov.b64 %0, {%1, %2};" : "=l"(r) : "f"(x), "f"(y));
    return r;
}
__device__ __forceinline__ float2 u64_as_f2(unsigned long long v) {
    float2 r;
    asm("mov.b64 {%0, %1}, %2;" : "=f"(r.x), "=f"(r.y) : "l"(v));
    return r;
}
__device__ __forceinline__ unsigned long long ffma2(unsigned long long a,
                                                    unsigned long long b,
                                                    unsigned long long c) {
    unsigned long long d;
    asm("fma.rn.f32x2 %0, %1, %2, %3;" : "=l"(d) : "l"(a), "l"(b), "l"(c));
    return d;
}

// ---------------------------------------------------------------------------
// Pass 1: per-(b,m) weight histogram over the 64x64 grid.
// One CTA per (b,m); smem atomics; 1/P folded in.
// ---------------------------------------------------------------------------
__global__ void __launch_bounds__(256) pass1_weights(
    const float* __restrict__ coords)   // [B, M, P, 2]
{
    __shared__ float wloc[HW];
    const int bm  = blockIdx.x;     // 0..255
    const int tid = threadIdx.x;

    #pragma unroll 4
    for (int i = tid; i < HW; i += 256) wloc[i] = 0.0f;
    __syncthreads();

    const float* cp = coords + (size_t)bm * P * 2;
    const float invP = 1.0f / (float)P;
    const float s = (float)(HDIM - 1);   // 63

    for (int p = tid; p < P; p += 256) {
        float yn = cp[p * 2 + 0];
        float xn = cp[p * 2 + 1];
        float y = yn * s;
        float x = xn * s;
        float x0f = floorf(x), y0f = floorf(y);
        float wx = x - x0f, wy = y - y0f;
        int ix0 = min(max((int)x0f, 0), HDIM - 1);
        int ix1 = min(ix0 + 1, HDIM - 1);
        int iy0 = min(max((int)y0f, 0), HDIM - 1);
        int iy1 = min(iy0 + 1, HDIM - 1);
        float w00 = (1.0f - wx) * (1.0f - wy) * invP;
        float w01 = wx * (1.0f - wy) * invP;
        float w10 = (1.0f - wx) * wy * invP;
        float w11 = wx * wy * invP;
        atomicAdd(&wloc[iy0 * HDIM + ix0], w00);
        atomicAdd(&wloc[iy0 * HDIM + ix1], w01);
        atomicAdd(&wloc[iy1 * HDIM + ix0], w10);
        atomicAdd(&wloc[iy1 * HDIM + ix1], w11);
    }
    __syncthreads();

    float* wout = g_W + (size_t)bm * HW;
    #pragma unroll 4
    for (int i = tid; i < HW; i += 256) wout[i] = wloc[i];
}

// ---------------------------------------------------------------------------
// Pass 2: per (chunk, b): partial[chunk][b][m][cpair] = sum over 128 pixels of
//         W[b][m][pix] * F[b][pix][cpair]
// 512 threads; thread owns channel pair = tid; 32 packed accumulators.
// Weights staged in smem as [m][pix] float2 with the scalar duplicated into
// both lanes so FFMA2 can consume them directly; inner loop reads 2 pixels'
// worth per LDS.128 (broadcast, conflict-free).
// ---------------------------------------------------------------------------
__global__ void __launch_bounds__(512, 1) pass2_contract(
    const float* __restrict__ F)        // [B, HW, C]
{
    __shared__ float2 w2[M][PIXPC];     // 32 KB, [mask][local pixel], value duplicated

    const int chunk = blockIdx.x;       // 0..NCHUNK-1
    const int b     = blockIdx.y;       // 0..B-1
    const int tid   = threadIdx.x;      // 0..511
    const int pixBase = chunk * PIXPC;

    // Stage + duplicate weights (coalesced global reads: consecutive tid -> consecutive pix)
    const float* Wb = g_W + (size_t)b * M * HW + pixBase;
    for (int i = tid; i < M * PIXPC; i += 512) {
        int m  = i >> 7;            // i / PIXPC
        int px = i & (PIXPC - 1);
        float v = Wb[(size_t)m * HW + px];
        w2[m][px] = make_float2(v, v);
    }
    __syncthreads();

    // Feature pointer for this (b, chunk), this thread's channel pair
    const float2* Fb = reinterpret_cast<const float2*>(
        F + ((size_t)b * HW + pixBase) * C) + tid;

    unsigned long long acc[M];
    #pragma unroll
    for (int m = 0; m < M; m++) acc[m] = 0ull;

    for (int p = 0; p < PIXPC; p += 2) {
        float2 f0 = Fb[(size_t)p * CPAIR];
        float2 f1 = Fb[(size_t)(p + 1) * CPAIR];
        unsigned long long f0l = f2_as_u64(f0.x, f0.y);
        unsigned long long f1l = f2_as_u64(f1.x, f1.y);
        #pragma unroll
        for (int m = 0; m < M; m++) {
            // LDS.128: {w[m][p] dup, w[m][p+1] dup}
            ulonglong2 wv = *reinterpret_cast<const ulonglong2*>(&w2[m][p]);
            acc[m] = ffma2(wv.x, f0l, acc[m]);
            acc[m] = ffma2(wv.y, f1l, acc[m]);
        }
    }

    // Write partials: [chunk][b*M + m][cpair]
    float2* out = g_partial + ((size_t)chunk * B * M + (size_t)b * M) * CPAIR + tid;
    #pragma unroll
    for (int m = 0; m < M; m++) {
        out[(size_t)m * CPAIR] = u64_as_f2(acc[m]);
    }
}

// ---------------------------------------------------------------------------
// Pass 3: reduce NCHUNK partials -> d_out  [B, M, 1, C] f32
// ---------------------------------------------------------------------------
__global__ void __launch_bounds__(256) pass3_reduce(float* __restrict__ out)
{
    int idx = blockIdx.x * 256 + threadIdx.x;   // over B*M*CPAIR float2 = 131072
    const int total = B * M * CPAIR;
    if (idx >= total) return;
    float sx = 0.0f, sy = 0.0f;
    #pragma unroll
    for (int ch = 0; ch < NCHUNK; ch++) {
        float2 v = g_partial[(size_t)ch * total + idx];
        sx += v.x;
        sy += v.y;
    }
    reinterpret_cast<float2*>(out)[idx] = make_float2(sx, sy);
}

// ---------------------------------------------------------------------------
extern "C" void kernel_launch(void* const* d_in, const int* in_sizes, int n_in,
                              void* d_out, int out_size)
{
    const float* feature = (const float*)d_in[0];
    const float* coords  = (const float*)d_in[1];
    // Safety: inputs identified by size (feature_map = 33554432, coords = 262144)
    if (n_in >= 2 && in_sizes[0] == B * M * P * 2) {
        feature = (const float*)d_in[1];
        coords  = (const float*)d_in[0];
    }

    pass1_weights<<<B * M, 256>>>(coords);

    dim3 g2(NCHUNK, B);
    pass2_contract<<<g2, 512>>>(feature);

    const int total_pairs = B * M * CPAIR;        // 131072
    pass3_reduce<<<(total_pairs + 255) / 256, 256>>>((float*)d_out);
}

// round 2
// speedup vs baseline: 1.2713x; 1.2713x over previous
#include <cuda_runtime.h>
#include <cstdint>

// Problem constants
#define B  8
#define HW 4096
#define HDIM 64
#define C  1024
#define M  32
#define P  512

#define NCHUNK 32
#define PIXPC  (HW / NCHUNK)   // 128 pixels per chunk
#define MH     16              // m's per CTA (half of M)
#define C4     (C / 4)         // 256 float4 channel quads

// Scratch: weights [B*M][HW] (4 MB) and partial sums [NCHUNK][B*M][C] (33.5 MB)
__device__ float g_W[(size_t)B * M * HW];
__device__ float g_partial[(size_t)NCHUNK * B * M * C];

// ---------------------------------------------------------------------------
// packed f32x2 helpers (sm_103a FFMA2 path — full-rate fp32)
// ---------------------------------------------------------------------------
__device__ __forceinline__ unsigned long long f2pack(float x, float y) {
    unsigned long long r;
    asm("mov.b64 %0, {%1, %2};" : "=l"(r) : "f"(x), "f"(y));
    return r;
}
__device__ __forceinline__ void f2unpack(unsigned long long v, float& x, float& y) {
    asm("mov.b64 {%0, %1}, %2;" : "=f"(x), "=f"(y) : "l"(v));
}
__device__ __forceinline__ unsigned long long ffma2(unsigned long long a,
                                                    unsigned long long b,
                                                    unsigned long long c) {
    unsigned long long d;
    asm("fma.rn.f32x2 %0, %1, %2, %3;" : "=l"(d) : "l"(a), "l"(b), "l"(c));
    return d;
}

// ---------------------------------------------------------------------------
// Pass 1: per-(b,m) weight histogram over the 64x64 grid.
// One CTA per (b,m); smem atomics; 1/P folded in.
// ---------------------------------------------------------------------------
__global__ void __launch_bounds__(256) pass1_weights(
    const float* __restrict__ coords)   // [B, M, P, 2]
{
    __shared__ float wloc[HW];
    const int bm  = blockIdx.x;     // 0..255
    const int tid = threadIdx.x;

    #pragma unroll 4
    for (int i = tid; i < HW; i += 256) wloc[i] = 0.0f;
    __syncthreads();

    const float* cp = coords + (size_t)bm * P * 2;
    const float invP = 1.0f / (float)P;
    const float s = (float)(HDIM - 1);   // 63

    for (int p = tid; p < P; p += 256) {
        float yn = cp[p * 2 + 0];
        float xn = cp[p * 2 + 1];
        float y = yn * s;
        float x = xn * s;
        float x0f = floorf(x), y0f = floorf(y);
        float wx = x - x0f, wy = y - y0f;
        int ix0 = min(max((int)x0f, 0), HDIM - 1);
        int ix1 = min(ix0 + 1, HDIM - 1);
        int iy0 = min(max((int)y0f, 0), HDIM - 1);
        int iy1 = min(iy0 + 1, HDIM - 1);
        float w00 = (1.0f - wx) * (1.0f - wy) * invP;
        float w01 = wx * (1.0f - wy) * invP;
        float w10 = (1.0f - wx) * wy * invP;
        float w11 = wx * wy * invP;
        atomicAdd(&wloc[iy0 * HDIM + ix0], w00);
        atomicAdd(&wloc[iy0 * HDIM + ix1], w01);
        atomicAdd(&wloc[iy1 * HDIM + ix0], w10);
        atomicAdd(&wloc[iy1 * HDIM + ix1], w11);
    }
    __syncthreads();

    float* wout = g_W + (size_t)bm * HW;
    #pragma unroll 4
    for (int i = tid; i < HW; i += 256) wout[i] = wloc[i];
}

// ---------------------------------------------------------------------------
// Pass 2: per (chunk, mhalf, b):
//   partial[chunk][b][m0+m][c] = sum over 128 pixels of W[b][m][pix]*F[b][pix][c]
// 256 threads; thread owns a float4 channel quad (tid); MH=16 m's per CTA.
// Per 2 pixels per m: 1 LDS.128 (2 duplicated weights) + 4 FFMA2  (1:4 ratio).
// Accumulators: 16 m x 2 u64 = 64 regs -> no spills, 2 CTAs/SM.
// Grid.x packs (chunk, mhalf) adjacently so the m-half pair shares F via L2.
// ---------------------------------------------------------------------------
__global__ void __launch_bounds__(256, 2) pass2_contract(
    const float* __restrict__ F)        // [B, HW, C]
{
    __shared__ __align__(16) float2 w2[MH][PIXPC];   // 16 KB, value duplicated

    const int cm    = blockIdx.x;        // 0..63  = chunk*2 + mhalf
    const int chunk = cm >> 1;
    const int m0    = (cm & 1) * MH;
    const int b     = blockIdx.y;        // 0..7
    const int tid   = threadIdx.x;       // 0..255
    const int pixBase = chunk * PIXPC;

    // Stage + duplicate weights (coalesced: consecutive tid -> consecutive pix)
    const float* Wb = g_W + ((size_t)(b * M + m0)) * HW + pixBase;
    #pragma unroll
    for (int i = tid; i < MH * PIXPC; i += 256) {
        int m  = i >> 7;             // i / PIXPC
        int px = i & (PIXPC - 1);
        float v = Wb[(size_t)m * HW + px];
        w2[m][px] = make_float2(v, v);
    }
    __syncthreads();

    // Feature pointer for this (b, chunk), this thread's channel quad
    const float4* Fb = reinterpret_cast<const float4*>(
        F + ((size_t)b * HW + pixBase) * C) + tid;

    unsigned long long accA[MH], accB[MH];
    #pragma unroll
    for (int m = 0; m < MH; m++) { accA[m] = 0ull; accB[m] = 0ull; }

    // Software-pipelined over pixel pairs
    float4 f0 = Fb[0];
    float4 f1 = Fb[C4];
    for (int p = 0; p < PIXPC; p += 2) {
        // Prefetch next pair (clamped to stay in-bounds on the last iteration)
        int pn = (p + 2 < PIXPC) ? (p + 2) : p;
        float4 n0 = Fb[(size_t)pn * C4];
        float4 n1 = Fb[(size_t)(pn + 1) * C4];

        unsigned long long f0a = f2pack(f0.x, f0.y);
        unsigned long long f0b = f2pack(f0.z, f0.w);
        unsigned long long f1a = f2pack(f1.x, f1.y);
        unsigned long long f1b = f2pack(f1.z, f1.w);

        #pragma unroll
        for (int m = 0; m < MH; m++) {
            // LDS.128 broadcast: {w[m][p] dup, w[m][p+1] dup}
            ulonglong2 wv = *reinterpret_cast<const ulonglong2*>(&w2[m][p]);
            accA[m] = ffma2(wv.x, f0a, accA[m]);
            accB[m] = ffma2(wv.x, f0b, accB[m]);
            accA[m] = ffma2(wv.y, f1a, accA[m]);
            accB[m] = ffma2(wv.y, f1b, accB[m]);
        }
        f0 = n0; f1 = n1;
    }

    // Write partials: [chunk][b*M + m0 + m][channel quad tid]
    float4* out = reinterpret_cast<float4*>(
        g_partial + ((size_t)chunk * B * M + (size_t)b * M + m0) * C) + tid;
    #pragma unroll
    for (int m = 0; m < MH; m++) {
        float4 v;
        f2unpack(accA[m], v.x, v.y);
        f2unpack(accB[m], v.z, v.w);
        out[(size_t)m * C4] = v;
    }
}

// ---------------------------------------------------------------------------
// Pass 3: reduce NCHUNK partials -> d_out  [B, M, 1, C] f32
// ---------------------------------------------------------------------------
__global__ void __launch_bounds__(256) pass3_reduce(float* __restrict__ out)
{
    const int total4 = B * M * C / 4;               // 65536 float4 slots
    int idx = blockIdx.x * 256 + threadIdx.x;
    if (idx >= total4) return;
    float4 s = make_float4(0.f, 0.f, 0.f, 0.f);
    const float4* part = reinterpret_cast<const float4*>(g_partial);
    #pragma unroll
    for (int ch = 0; ch < NCHUNK; ch++) {
        float4 v = part[(size_t)ch * total4 + idx];
        s.x += v.x; s.y += v.y; s.z += v.z; s.w += v.w;
    }
    reinterpret_cast<float4*>(out)[idx] = s;
}

// ---------------------------------------------------------------------------
extern "C" void kernel_launch(void* const* d_in, const int* in_sizes, int n_in,
                              void* d_out, int out_size)
{
    const float* feature = (const float*)d_in[0];
    const float* coords  = (const float*)d_in[1];
    // Safety: inputs identified by size (feature_map = 33554432, coords = 262144)
    if (n_in >= 2 && in_sizes[0] == B * M * P * 2) {
        feature = (const float*)d_in[1];
        coords  = (const float*)d_in[0];
    }

    pass1_weights<<<B * M, 256>>>(coords);

    dim3 g2(NCHUNK * 2, B);                         // (chunk, mhalf) x batch
    pass2_contract<<<g2, 256>>>(feature);

    const int total4 = B * M * C / 4;               // 65536
    pass3_reduce<<<(total4 + 255) / 256, 256>>>((float*)d_out);
}

// round 4
// speedup vs baseline: 2.1083x; 1.6584x over previous
#include <cuda_runtime.h>
#include <cstdint>

// ---------------- problem constants ----------------
#define B_    8
#define HW_   4096
#define HDIM_ 64
#define C_    1024
#define M_    32
#define P_    512

// ---------------- GEMM tiling ----------------
#define NTILE   64                  // channels per CTA
#define NBLKS   (C_ / NTILE)        // 16
#define KC      32                  // k (pixels) per chunk
#define NCHUNK  (HW_ / KC)          // 128
#define NSTAGE  4

// smem strides (in 32-bit words) — chosen for conflict-free fragment LDS
// and 16B-aligned cp.async rows.
#define FS 72                       // F tile row stride: row = 64 ch + 8 pad
#define WS 40                       // W tile row stride: row = 32 k + 8 pad
#define FBYTES (KC * FS * 4)        // 9216
#define WBYTES (M_ * WS * 4)        // 5120
#define STAGE_BYTES (FBYTES + WBYTES)       // 14336
#define SMEM_TOTAL (NSTAGE * STAGE_BYTES)   // 57344

// Scratch: tf32(RNA)-rounded weights [B][M][HW]
__device__ float g_W[(size_t)B_ * M_ * HW_];

// ---------------- helpers ----------------
__device__ __forceinline__ uint32_t smem_u32(const void* p) {
    uint32_t a;
    asm("{ .reg .u64 t; cvta.to.shared.u64 t, %1; cvt.u32.u64 %0, t; }" : "=r"(a) : "l"(p));
    return a;
}
__device__ __forceinline__ void cp_async16(uint32_t dst, const void* src) {
    asm volatile("cp.async.cg.shared.global [%0], [%1], 16;" :: "r"(dst), "l"(src));
}
#define CP_COMMIT() asm volatile("cp.async.commit_group;" ::: "memory")
#define CP_WAIT2()  asm volatile("cp.async.wait_group 2;" ::: "memory")

__device__ __forceinline__ uint32_t to_tf32(float x) {
    uint32_t r;
    asm("cvt.rna.tf32.f32 %0, %1;" : "=r"(r) : "f"(x));
    return r;
}

// D[16ch x 8m] += A[16ch x 8k] * B[8k x 8m]   (tf32, fp32 accum)
__device__ __forceinline__ void mma_tf32(float& d0, float& d1, float& d2, float& d3,
                                         uint32_t a0, uint32_t a1, uint32_t a2, uint32_t a3,
                                         uint32_t b0, uint32_t b1) {
    asm volatile(
        "mma.sync.aligned.m16n8k8.row.col.f32.tf32.tf32.f32 "
        "{%0,%1,%2,%3}, {%4,%5,%6,%7}, {%8,%9}, {%0,%1,%2,%3};"
        : "+f"(d0), "+f"(d1), "+f"(d2), "+f"(d3)
        : "r"(a0), "r"(a1), "r"(a2), "r"(a3), "r"(b0), "r"(b1));
}

// ---------------------------------------------------------------------------
// Pass 1: per-(b,m) weight histogram over the 64x64 grid, RNA-rounded to tf32.
// ---------------------------------------------------------------------------
__global__ void __launch_bounds__(256) pass1_weights(
    const float* __restrict__ coords)   // [B, M, P, 2]
{
    __shared__ float wloc[HW_];
    const int bm  = blockIdx.x;     // 0..255
    const int tid = threadIdx.x;

    #pragma unroll 4
    for (int i = tid; i < HW_; i += 256) wloc[i] = 0.0f;
    __syncthreads();

    const float* cp = coords + (size_t)bm * P_ * 2;
    const float invP = 1.0f / (float)P_;
    const float s = (float)(HDIM_ - 1);

    for (int p = tid; p < P_; p += 256) {
        float yn = cp[p * 2 + 0];
        float xn = cp[p * 2 + 1];
        float y = yn * s;
        float x = xn * s;
        float x0f = floorf(x), y0f = floorf(y);
        float wx = x - x0f, wy = y - y0f;
        int ix0 = min(max((int)x0f, 0), HDIM_ - 1);
        int ix1 = min(ix0 + 1, HDIM_ - 1);
        int iy0 = min(max((int)y0f, 0), HDIM_ - 1);
        int iy1 = min(iy0 + 1, HDIM_ - 1);
        float w00 = (1.0f - wx) * (1.0f - wy) * invP;
        float w01 = wx * (1.0f - wy) * invP;
        float w10 = (1.0f - wx) * wy * invP;
        float w11 = wx * wy * invP;
        atomicAdd(&wloc[iy0 * HDIM_ + ix0], w00);
        atomicAdd(&wloc[iy0 * HDIM_ + ix1], w01);
        atomicAdd(&wloc[iy1 * HDIM_ + ix0], w10);
        atomicAdd(&wloc[iy1 * HDIM_ + ix1], w11);
    }
    __syncthreads();

    float* wout = g_W + (size_t)bm * HW_;
    #pragma unroll 4
    for (int i = tid; i < HW_; i += 256) {
        wout[i] = __uint_as_float(to_tf32(wloc[i]));
    }
}

// ---------------------------------------------------------------------------
// Pass 2: tf32 HMMA GEMM via mma.sync.m16n8k8.
// CTA (nblk, b): D[32m x 64ch] = W[32m x 4096k] @ F[4096k x 64ch-slice]
//   mma roles: A = F (16 ch x 8 k, row-major), B = W (8 k x 8 m, col-major)
// Warp w (8 per CTA): ntile = w&3 (16 ch), mpair = w>>2 (2 mma: m0, m0+8).
// 4-stage cp.async pipeline over 128 K-chunks of 32.
// ---------------------------------------------------------------------------
__global__ void __launch_bounds__(256, 1) pass2_mma(
    const float* __restrict__ F,        // [B, HW, C]
    float* __restrict__ out)            // [B, M, 1, C]
{
    extern __shared__ char smem[];
    const uint32_t sbase = smem_u32(smem);

    const int tid  = threadIdx.x;
    const int lane = tid & 31;
    const int wid  = tid >> 5;
    const int nblk = blockIdx.x;        // 0..15
    const int b    = blockIdx.y;        // 0..7
    const int c0   = nblk * NTILE;

    const int r = lane >> 2;            // 0..7
    const int c = lane & 3;             // 0..3
    const int n0ch = (wid & 3) * 16;    // channel offset within tile
    const int m0   = (wid >> 2) * 16;   // mask offset (mma j adds j*8)

    const float* Fb = F + (size_t)b * HW_ * C_ + c0;
    const float* Wb = g_W + (size_t)b * M_ * HW_;

    // ---- chunk loader: F tile [32k x 64ch] + W tile [32m x 32k] ----
    auto load_chunk = [&](int chunk) {
        const int s  = chunk & (NSTAGE - 1);
        const int k0 = chunk * KC;
        const uint32_t fb = sbase + s * STAGE_BYTES;
        const uint32_t wb = fb + FBYTES;
        // F: 512 x 16B units; thread u -> units u, u+256
        #pragma unroll
        for (int h = 0; h < 2; h++) {
            int unit = tid + h * 256;
            int row = unit >> 4;        // local k 0..31
            int uc  = unit & 15;        // 16B unit within 64-ch row
            cp_async16(fb + (uint32_t)(row * (FS * 4) + uc * 16),
                       Fb + (size_t)(k0 + row) * C_ + uc * 4);
        }
        // W: 256 x 16B units; thread u -> (m = u>>3, kq = u&7)
        {
            int m  = tid >> 3;
            int kq = tid & 7;
            cp_async16(wb + (uint32_t)(m * (WS * 4) + kq * 16),
                       Wb + (size_t)m * HW_ + k0 + kq * 4);
        }
    };

    // prologue: 3 chunks in flight
    load_chunk(0); CP_COMMIT();
    load_chunk(1); CP_COMMIT();
    load_chunk(2); CP_COMMIT();

    float d00 = 0.f, d01 = 0.f, d02 = 0.f, d03 = 0.f;   // mma j=0 (m0)
    float d10 = 0.f, d11 = 0.f, d12 = 0.f, d13 = 0.f;   // mma j=1 (m0+8)

    for (int i = 0; i < NCHUNK; i++) {
        CP_WAIT2();                 // chunk i resident
        __syncthreads();

        const float* fptr = reinterpret_cast<const float*>(smem + (i & (NSTAGE - 1)) * STAGE_BYTES);
        const float* wptr = fptr + KC * FS;

        #pragma unroll
        for (int ks = 0; ks < KC / 8; ks++) {
            const int kr = ks * 8;
            // A = F fragments (16ch x 8k), rounded to tf32
            uint32_t a0 = to_tf32(fptr[(kr + c) * FS + n0ch + r]);
            uint32_t a1 = to_tf32(fptr[(kr + c) * FS + n0ch + r + 8]);
            uint32_t a2 = to_tf32(fptr[(kr + c + 4) * FS + n0ch + r]);
            uint32_t a3 = to_tf32(fptr[(kr + c + 4) * FS + n0ch + r + 8]);
            // B = W fragments (8k x 8m), already tf32 from pass1
            uint32_t b00 = __float_as_uint(wptr[(m0 + r) * WS + kr + c]);
            uint32_t b01 = __float_as_uint(wptr[(m0 + r) * WS + kr + c + 4]);
            uint32_t b10 = __float_as_uint(wptr[(m0 + 8 + r) * WS + kr + c]);
            uint32_t b11 = __float_as_uint(wptr[(m0 + 8 + r) * WS + kr + c + 4]);

            mma_tf32(d00, d01, d02, d03, a0, a1, a2, a3, b00, b01);
            mma_tf32(d10, d11, d12, d13, a0, a1, a2, a3, b10, b11);
        }

        if (i + 3 < NCHUNK) load_chunk(i + 3);
        CP_COMMIT();                // one group per iteration (may be empty)
    }

    // ---- epilogue: D[ch = n0ch + r (+8)][m = m0(+8) + 2c (+1)] ----
    float* ob = out + (size_t)b * M_ * C_ + c0;
    const int ch = n0ch + r;
    {
        int mA = m0 + 2 * c, mB = mA + 1;
        ob[(size_t)mA * C_ + ch]     = d00;
        ob[(size_t)mB * C_ + ch]     = d01;
        ob[(size_t)mA * C_ + ch + 8] = d02;
        ob[(size_t)mB * C_ + ch + 8] = d03;
    }
    {
        int mA = m0 + 8 + 2 * c, mB = mA + 1;
        ob[(size_t)mA * C_ + ch]     = d10;
        ob[(size_t)mB * C_ + ch]     = d11;
        ob[(size_t)mA * C_ + ch + 8] = d12;
        ob[(size_t)mB * C_ + ch + 8] = d13;
    }
}

// ---------------------------------------------------------------------------
extern "C" void kernel_launch(void* const* d_in, const int* in_sizes, int n_in,
                              void* d_out, int out_size)
{
    const float* feature = (const float*)d_in[0];
    const float* coords  = (const float*)d_in[1];
    if (n_in >= 2 && in_sizes[0] == B_ * M_ * P_ * 2) {
        feature = (const float*)d_in[1];
        coords  = (const float*)d_in[0];
    }

    cudaFuncSetAttribute(pass2_mma, cudaFuncAttributeMaxDynamicSharedMemorySize, SMEM_TOTAL);

    pass1_weights<<<B_ * M_, 256>>>(coords);

    dim3 g2(NBLKS, B_);
    pass2_mma<<<g2, 256, SMEM_TOTAL>>>(feature, (float*)d_out);
}

// round 5
// speedup vs baseline: 2.2912x; 1.0868x over previous
#include <cuda_runtime.h>
#include <cstdint>

// ---------------- problem constants ----------------
#define B_    8
#define HW_   4096
#define HDIM_ 64
#define C_    1024
#define M_    32
#define P_    512

// ---------------- GEMM tiling ----------------
#define NTILE   64                  // channels per CTA
#define NBLKS   (C_ / NTILE)        // 16
#define KC      32                  // k (pixels) per chunk
#define KSPLIT  2                   // K split across grid.z
#define KHALF   (HW_ / KSPLIT)      // 2048
#define NCHUNK  (KHALF / KC)        // 64 chunks per CTA
#define NSTAGE  4

// smem strides (in 32-bit words) — conflict-free fragment LDS, 16B-aligned rows
#define FS 72                       // F tile row stride: 64 ch + 8 pad
#define WS 40                       // W tile row stride: 32 k + 8 pad
#define FBYTES (KC * FS * 4)        // 9216
#define WBYTES (M_ * WS * 4)        // 5120
#define STAGE_BYTES (FBYTES + WBYTES)       // 14336
#define SMEM_TOTAL (NSTAGE * STAGE_BYTES)   // 57344

// Scratch: tf32(RNA)-rounded weights [B][M][HW]; K-split partials
__device__ float g_W[(size_t)B_ * M_ * HW_];
__device__ float g_part[(size_t)KSPLIT * B_ * M_ * C_];

// ---------------- helpers ----------------
__device__ __forceinline__ uint32_t smem_u32(const void* p) {
    uint32_t a;
    asm("{ .reg .u64 t; cvta.to.shared.u64 t, %1; cvt.u32.u64 %0, t; }" : "=r"(a) : "l"(p));
    return a;
}
__device__ __forceinline__ void cp_async16(uint32_t dst, const void* src) {
    asm volatile("cp.async.cg.shared.global [%0], [%1], 16;" :: "r"(dst), "l"(src));
}
#define CP_COMMIT() asm volatile("cp.async.commit_group;" ::: "memory")
#define CP_WAIT2()  asm volatile("cp.async.wait_group 2;" ::: "memory")

__device__ __forceinline__ uint32_t to_tf32(float x) {
    uint32_t r;
    asm("cvt.rna.tf32.f32 %0, %1;" : "=r"(r) : "f"(x));
    return r;
}

// D[16ch x 8m] += A[16ch x 8k] * B[8k x 8m]   (tf32, fp32 accum)
__device__ __forceinline__ void mma_tf32(float& d0, float& d1, float& d2, float& d3,
                                         uint32_t a0, uint32_t a1, uint32_t a2, uint32_t a3,
                                         uint32_t b0, uint32_t b1) {
    asm volatile(
        "mma.sync.aligned.m16n8k8.row.col.f32.tf32.tf32.f32 "
        "{%0,%1,%2,%3}, {%4,%5,%6,%7}, {%8,%9}, {%0,%1,%2,%3};"
        : "+f"(d0), "+f"(d1), "+f"(d2), "+f"(d3)
        : "r"(a0), "r"(a1), "r"(a2), "r"(a3), "r"(b0), "r"(b1));
}

// ---------------------------------------------------------------------------
// Pass 1: per-(b,m) weight histogram over the 64x64 grid, RNA-rounded to tf32.
// ---------------------------------------------------------------------------
__global__ void __launch_bounds__(256) pass1_weights(
    const float* __restrict__ coords)   // [B, M, P, 2]
{
    __shared__ float wloc[HW_];
    const int bm  = blockIdx.x;     // 0..255
    const int tid = threadIdx.x;

    #pragma unroll 4
    for (int i = tid; i < HW_; i += 256) wloc[i] = 0.0f;
    __syncthreads();

    const float* cp = coords + (size_t)bm * P_ * 2;
    const float invP = 1.0f / (float)P_;
    const float s = (float)(HDIM_ - 1);

    for (int p = tid; p < P_; p += 256) {
        float yn = cp[p * 2 + 0];
        float xn = cp[p * 2 + 1];
        float y = yn * s;
        float x = xn * s;
        float x0f = floorf(x), y0f = floorf(y);
        float wx = x - x0f, wy = y - y0f;
        int ix0 = min(max((int)x0f, 0), HDIM_ - 1);
        int ix1 = min(ix0 + 1, HDIM_ - 1);
        int iy0 = min(max((int)y0f, 0), HDIM_ - 1);
        int iy1 = min(iy0 + 1, HDIM_ - 1);
        float w00 = (1.0f - wx) * (1.0f - wy) * invP;
        float w01 = wx * (1.0f - wy) * invP;
        float w10 = (1.0f - wx) * wy * invP;
        float w11 = wx * wy * invP;
        atomicAdd(&wloc[iy0 * HDIM_ + ix0], w00);
        atomicAdd(&wloc[iy0 * HDIM_ + ix1], w01);
        atomicAdd(&wloc[iy1 * HDIM_ + ix0], w10);
        atomicAdd(&wloc[iy1 * HDIM_ + ix1], w11);
    }
    __syncthreads();

    float* wout = g_W + (size_t)bm * HW_;
    #pragma unroll 4
    for (int i = tid; i < HW_; i += 256) {
        wout[i] = __uint_as_float(to_tf32(wloc[i]));
    }
}

// ---------------------------------------------------------------------------
// Pass 2: tf32 HMMA GEMM via mma.sync.m16n8k8, K-split across grid.z.
// CTA (nblk, b, ksp): partial D[32m x 64ch] over k in [ksp*2048, +2048)
//   mma roles: A = F (16 ch x 8 k, row-major), B = W (8 k x 8 m, col-major)
// ---------------------------------------------------------------------------
__global__ void __launch_bounds__(256, 2) pass2_mma(
    const float* __restrict__ F)        // [B, HW, C]
{
    extern __shared__ char smem[];
    const uint32_t sbase = smem_u32(smem);

    const int tid  = threadIdx.x;
    const int lane = tid & 31;
    const int wid  = tid >> 5;
    const int nblk = blockIdx.x;        // 0..15
    const int b    = blockIdx.y;        // 0..7
    const int ksp  = blockIdx.z;        // 0..1
    const int c0   = nblk * NTILE;
    const int kbase = ksp * KHALF;

    const int r = lane >> 2;            // 0..7
    const int c = lane & 3;             // 0..3
    const int n0ch = (wid & 3) * 16;    // channel offset within tile
    const int m0   = (wid >> 2) * 16;   // mask offset (mma j adds j*8)

    const float* Fb = F + (size_t)b * HW_ * C_ + (size_t)kbase * C_ + c0;
    const float* Wb = g_W + (size_t)b * M_ * HW_ + kbase;

    // ---- chunk loader: F tile [32k x 64ch] + W tile [32m x 32k] ----
    auto load_chunk = [&](int chunk) {
        const int s  = chunk & (NSTAGE - 1);
        const int k0 = chunk * KC;
        const uint32_t fb = sbase + s * STAGE_BYTES;
        const uint32_t wb = fb + FBYTES;
        // F: 512 x 16B units
        #pragma unroll
        for (int h = 0; h < 2; h++) {
            int unit = tid + h * 256;
            int row = unit >> 4;        // local k 0..31
            int uc  = unit & 15;        // 16B unit within 64-ch row
            cp_async16(fb + (uint32_t)(row * (FS * 4) + uc * 16),
                       Fb + (size_t)(k0 + row) * C_ + uc * 4);
        }
        // W: 256 x 16B units
        {
            int m  = tid >> 3;
            int kq = tid & 7;
            cp_async16(wb + (uint32_t)(m * (WS * 4) + kq * 16),
                       Wb + (size_t)m * HW_ + k0 + kq * 4);
        }
    };

    // prologue: 3 chunks in flight
    load_chunk(0); CP_COMMIT();
    load_chunk(1); CP_COMMIT();
    load_chunk(2); CP_COMMIT();

    float d00 = 0.f, d01 = 0.f, d02 = 0.f, d03 = 0.f;   // mma j=0 (m0)
    float d10 = 0.f, d11 = 0.f, d12 = 0.f, d13 = 0.f;   // mma j=1 (m0+8)

    for (int i = 0; i < NCHUNK; i++) {
        CP_WAIT2();                 // chunk i resident
        __syncthreads();

        const float* fptr = reinterpret_cast<const float*>(smem + (i & (NSTAGE - 1)) * STAGE_BYTES);
        const float* wptr = fptr + KC * FS;

        #pragma unroll
        for (int ks = 0; ks < KC / 8; ks++) {
            const int kr = ks * 8;
            // A = F fragments (16ch x 8k), rounded to tf32
            uint32_t a0 = to_tf32(fptr[(kr + c) * FS + n0ch + r]);
            uint32_t a1 = to_tf32(fptr[(kr + c) * FS + n0ch + r + 8]);
            uint32_t a2 = to_tf32(fptr[(kr + c + 4) * FS + n0ch + r]);
            uint32_t a3 = to_tf32(fptr[(kr + c + 4) * FS + n0ch + r + 8]);
            // B = W fragments (8k x 8m), already tf32 from pass1
            uint32_t b00 = __float_as_uint(wptr[(m0 + r) * WS + kr + c]);
            uint32_t b01 = __float_as_uint(wptr[(m0 + r) * WS + kr + c + 4]);
            uint32_t b10 = __float_as_uint(wptr[(m0 + 8 + r) * WS + kr + c]);
            uint32_t b11 = __float_as_uint(wptr[(m0 + 8 + r) * WS + kr + c + 4]);

            mma_tf32(d00, d01, d02, d03, a0, a1, a2, a3, b00, b01);
            mma_tf32(d10, d11, d12, d13, a0, a1, a2, a3, b10, b11);
        }

        if (i + 3 < NCHUNK) load_chunk(i + 3);
        CP_COMMIT();                // one group per iteration (may be empty)
    }

    // ---- epilogue: write partials  D[ch = n0ch + r (+8)][m = m0(+8) + 2c (+1)]
    float* ob = g_part + ((size_t)ksp * B_ + b) * M_ * C_ + c0;
    const int ch = n0ch + r;
    {
        int mA = m0 + 2 * c, mB = mA + 1;
        ob[(size_t)mA * C_ + ch]     = d00;
        ob[(size_t)mB * C_ + ch]     = d01;
        ob[(size_t)mA * C_ + ch + 8] = d02;
        ob[(size_t)mB * C_ + ch + 8] = d03;
    }
    {
        int mA = m0 + 8 + 2 * c, mB = mA + 1;
        ob[(size_t)mA * C_ + ch]     = d10;
        ob[(size_t)mB * C_ + ch]     = d11;
        ob[(size_t)mA * C_ + ch + 8] = d12;
        ob[(size_t)mB * C_ + ch + 8] = d13;
    }
}

// ---------------------------------------------------------------------------
// Pass 3: reduce KSPLIT partials -> d_out  [B, M, 1, C] f32
// ---------------------------------------------------------------------------
__global__ void __launch_bounds__(256) pass3_reduce(float* __restrict__ out)
{
    const int total4 = B_ * M_ * C_ / 4;            // 65536 float4 slots
    int idx = blockIdx.x * 256 + threadIdx.x;
    if (idx >= total4) return;
    const float4* p0 = reinterpret_cast<const float4*>(g_part);
    const float4* p1 = p0 + total4;
    float4 a = p0[idx], bb = p1[idx];
    a.x += bb.x; a.y += bb.y; a.z += bb.z; a.w += bb.w;
    reinterpret_cast<float4*>(out)[idx] = a;
}

// ---------------------------------------------------------------------------
extern "C" void kernel_launch(void* const* d_in, const int* in_sizes, int n_in,
                              void* d_out, int out_size)
{
    const float* feature = (const float*)d_in[0];
    const float* coords  = (const float*)d_in[1];
    if (n_in >= 2 && in_sizes[0] == B_ * M_ * P_ * 2) {
        feature = (const float*)d_in[1];
        coords  = (const float*)d_in[0];
    }

    cudaFuncSetAttribute(pass2_mma, cudaFuncAttributeMaxDynamicSharedMemorySize, SMEM_TOTAL);

    pass1_weights<<<B_ * M_, 256>>>(coords);

    dim3 g2(NBLKS, B_, KSPLIT);
    pass2_mma<<<g2, 256, SMEM_TOTAL>>>(feature);

    const int total4 = B_ * M_ * C_ / 4;            // 65536
    pass3_reduce<<<(total4 + 255) / 256, 256>>>((float*)d_out);
}

// round 6
// speedup vs baseline: 3.0861x; 1.3469x over previous
#include <cuda_runtime.h>
#include <cstdint>

// ---------------- problem constants ----------------
#define B_    8
#define HW_   4096
#define HDIM_ 64
#define C_    1024
#define M_    32
#define P_    512

// ---------------- GEMM tiling ----------------
#define CTILE   256                 // channels per CTA
#define NBLKS   (C_ / CTILE)        // 4
#define KSPLIT  8                   // K split across grid.z
#define KRANGE  (HW_ / KSPLIT)      // 512 k per CTA
#define KC      16                  // k (pixels) per chunk
#define NCHUNK  (KRANGE / KC)       // 32 chunks per CTA
#define NSTAGE  4

// smem strides (words) — conflict-free fragment LDS, 16B-aligned rows
#define FSW 264                     // F row stride: 256 ch + 8 pad  (264%32=8)
#define WSW 36                      // W row stride: 16 k + 20 pad   (36%32=4)
#define FROWB (FSW * 4)             // 1056
#define WROWB (WSW * 4)             // 144
#define FBYTES (KC * FROWB)         // 16896
#define WBYTES (M_ * WROWB)         // 4608
#define STAGE_BYTES (FBYTES + WBYTES)       // 21504
#define SMEM_TOTAL (NSTAGE * STAGE_BYTES)   // 86016

// Scratch: tf32(RNA)-rounded weights [B][M][HW]; K-split partials
__device__ float g_W[(size_t)B_ * M_ * HW_];
__device__ float g_part[(size_t)KSPLIT * B_ * M_ * C_];

// ---------------- helpers ----------------
__device__ __forceinline__ uint32_t smem_u32(const void* p) {
    uint32_t a;
    asm("{ .reg .u64 t; cvta.to.shared.u64 t, %1; cvt.u32.u64 %0, t; }" : "=r"(a) : "l"(p));
    return a;
}
__device__ __forceinline__ void cp_async16(uint32_t dst, const void* src) {
    asm volatile("cp.async.cg.shared.global [%0], [%1], 16;" :: "r"(dst), "l"(src));
}
#define CP_COMMIT() asm volatile("cp.async.commit_group;" ::: "memory")
#define CP_WAIT2()  asm volatile("cp.async.wait_group 2;" ::: "memory")

__device__ __forceinline__ uint32_t to_tf32(float x) {
    uint32_t r;
    asm("cvt.rna.tf32.f32 %0, %1;" : "=r"(r) : "f"(x));
    return r;
}

// D[16ch x 8m] += A[16ch x 8k] * B[8k x 8m]   (tf32, fp32 accum)
__device__ __forceinline__ void mma_tf32(float* d,
                                         uint32_t a0, uint32_t a1, uint32_t a2, uint32_t a3,
                                         uint32_t b0, uint32_t b1) {
    asm volatile(
        "mma.sync.aligned.m16n8k8.row.col.f32.tf32.tf32.f32 "
        "{%0,%1,%2,%3}, {%4,%5,%6,%7}, {%8,%9}, {%0,%1,%2,%3};"
        : "+f"(d[0]), "+f"(d[1]), "+f"(d[2]), "+f"(d[3])
        : "r"(a0), "r"(a1), "r"(a2), "r"(a3), "r"(b0), "r"(b1));
}

// ---------------------------------------------------------------------------
// Pass 1: per-(b,m) weight histogram over the 64x64 grid, RNA-rounded to tf32.
// ---------------------------------------------------------------------------
__global__ void __launch_bounds__(256) pass1_weights(
    const float* __restrict__ coords)   // [B, M, P, 2]
{
    __shared__ float wloc[HW_];
    const int bm  = blockIdx.x;     // 0..255
    const int tid = threadIdx.x;

    #pragma unroll 4
    for (int i = tid; i < HW_; i += 256) wloc[i] = 0.0f;
    __syncthreads();

    const float* cp = coords + (size_t)bm * P_ * 2;
    const float invP = 1.0f / (float)P_;
    const float s = (float)(HDIM_ - 1);

    for (int p = tid; p < P_; p += 256) {
        float yn = cp[p * 2 + 0];
        float xn = cp[p * 2 + 1];
        float y = yn * s;
        float x = xn * s;
        float x0f = floorf(x), y0f = floorf(y);
        float wx = x - x0f, wy = y - y0f;
        int ix0 = min(max((int)x0f, 0), HDIM_ - 1);
        int ix1 = min(ix0 + 1, HDIM_ - 1);
        int iy0 = min(max((int)y0f, 0), HDIM_ - 1);
        int iy1 = min(iy0 + 1, HDIM_ - 1);
        float w00 = (1.0f - wx) * (1.0f - wy) * invP;
        float w01 = wx * (1.0f - wy) * invP;
        float w10 = (1.0f - wx) * wy * invP;
        float w11 = wx * wy * invP;
        atomicAdd(&wloc[iy0 * HDIM_ + ix0], w00);
        atomicAdd(&wloc[iy0 * HDIM_ + ix1], w01);
        atomicAdd(&wloc[iy1 * HDIM_ + ix0], w10);
        atomicAdd(&wloc[iy1 * HDIM_ + ix1], w11);
    }
    __syncthreads();

    float* wout = g_W + (size_t)bm * HW_;
    #pragma unroll 4
    for (int i = tid; i < HW_; i += 256) {
        wout[i] = __uint_as_float(to_tf32(wloc[i]));
    }
}

// ---------------------------------------------------------------------------
// Pass 2: tf32 HMMA GEMM. CTA (nblk, b, ksp): partial D[32m x 256ch] over 512 k.
// 8 warps; warp w owns channels [w*32, w*32+32) x all 32 m:
//   per k-step: 2 A-sets (F, 16ch x 8k) + 4 B-sets (W, 8k x 8m) -> 8 mma
//   LDS per mma = 2 (halved vs prior round: crossbar was the limiter).
// ---------------------------------------------------------------------------
__global__ void __launch_bounds__(256, 2) pass2_mma(
    const float* __restrict__ F)        // [B, HW, C]
{
    extern __shared__ char smem[];
    const uint32_t sbase = smem_u32(smem);

    const int tid  = threadIdx.x;
    const int lane = tid & 31;
    const int wid  = tid >> 5;          // 0..7
    const int nblk = blockIdx.x;        // 0..3
    const int b    = blockIdx.y;        // 0..7
    const int ksp  = blockIdx.z;        // 0..7
    const int c0   = nblk * CTILE;
    const int kbase = ksp * KRANGE;

    const int r = lane >> 2;            // 0..7
    const int c = lane & 3;             // 0..3
    const int chw = wid * 32;           // warp channel base within tile

    const float* Fb = F + ((size_t)b * HW_ + kbase) * C_ + c0;
    const float* Wb = g_W + (size_t)b * M_ * HW_ + kbase;

    // ---- chunk loader: F tile [16k x 256ch] + W tile [32m x 16k] ----
    auto load_chunk = [&](int chunk) {
        const int s  = chunk & (NSTAGE - 1);
        const int k0 = chunk * KC;
        const uint32_t fb = sbase + s * STAGE_BYTES;
        const uint32_t wb = fb + FBYTES;
        // F: 1024 x 16B units
        #pragma unroll
        for (int h = 0; h < 4; h++) {
            int unit = tid + h * 256;
            int row = unit >> 6;        // local k 0..15
            int uc  = unit & 63;        // 16B unit within 256-ch row
            cp_async16(fb + (uint32_t)(row * FROWB + uc * 16),
                       Fb + (size_t)(k0 + row) * C_ + uc * 4);
        }
        // W: 128 x 16B units (threads 0..127)
        if (tid < 128) {
            int m  = tid >> 2;
            int kq = tid & 3;
            cp_async16(wb + (uint32_t)(m * WROWB + kq * 16),
                       Wb + (size_t)m * HW_ + k0 + kq * 4);
        }
    };

    // prologue: 3 chunks in flight
    load_chunk(0); CP_COMMIT();
    load_chunk(1); CP_COMMIT();
    load_chunk(2); CP_COMMIT();

    float d[2][4][4];
    #pragma unroll
    for (int t = 0; t < 2; t++)
        #pragma unroll
        for (int j = 0; j < 4; j++)
            #pragma unroll
            for (int e = 0; e < 4; e++) d[t][j][e] = 0.f;

    for (int i = 0; i < NCHUNK; i++) {
        CP_WAIT2();                 // chunk i resident
        __syncthreads();

        const float* fptr = reinterpret_cast<const float*>(smem + (i & (NSTAGE - 1)) * STAGE_BYTES);
        const float* wptr = fptr + KC * FSW;

        #pragma unroll
        for (int ks = 0; ks < KC / 8; ks++) {
            const int kr = ks * 8;
            // A = F fragments: 2 sets of 16 ch
            uint32_t a[2][4];
            #pragma unroll
            for (int t = 0; t < 2; t++) {
                const int chb = chw + t * 16;
                a[t][0] = to_tf32(fptr[(kr + c) * FSW + chb + r]);
                a[t][1] = to_tf32(fptr[(kr + c) * FSW + chb + r + 8]);
                a[t][2] = to_tf32(fptr[(kr + c + 4) * FSW + chb + r]);
                a[t][3] = to_tf32(fptr[(kr + c + 4) * FSW + chb + r + 8]);
            }
            // B = W fragments: 4 sets of 8 m (already tf32 from pass1)
            uint32_t bf[4][2];
            #pragma unroll
            for (int j = 0; j < 4; j++) {
                bf[j][0] = __float_as_uint(wptr[(j * 8 + r) * WSW + kr + c]);
                bf[j][1] = __float_as_uint(wptr[(j * 8 + r) * WSW + kr + c + 4]);
            }
            #pragma unroll
            for (int t = 0; t < 2; t++)
                #pragma unroll
                for (int j = 0; j < 4; j++)
                    mma_tf32(d[t][j], a[t][0], a[t][1], a[t][2], a[t][3],
                             bf[j][0], bf[j][1]);
        }

        if (i + 3 < NCHUNK) load_chunk(i + 3);
        CP_COMMIT();                // one group per iteration (may be empty)
    }

    // ---- epilogue: write partials ----
    // D element map per mma: thread (r,c) holds (ch=r, m=2c), (r, 2c+1), (r+8, 2c), (r+8, 2c+1)
    float* pb = g_part + ((size_t)(ksp * B_ + b)) * M_ * C_ + c0;
    #pragma unroll
    for (int t = 0; t < 2; t++) {
        const int ch = chw + t * 16 + r;
        #pragma unroll
        for (int j = 0; j < 4; j++) {
            int mA = j * 8 + 2 * c, mB = mA + 1;
            pb[(size_t)mA * C_ + ch]     = d[t][j][0];
            pb[(size_t)mB * C_ + ch]     = d[t][j][1];
            pb[(size_t)mA * C_ + ch + 8] = d[t][j][2];
            pb[(size_t)mB * C_ + ch + 8] = d[t][j][3];
        }
    }
}

// ---------------------------------------------------------------------------
// Pass 3: reduce KSPLIT partials -> d_out  [B, M, 1, C] f32
// ---------------------------------------------------------------------------
__global__ void __launch_bounds__(256) pass3_reduce(float* __restrict__ out)
{
    const int total4 = B_ * M_ * C_ / 4;            // 65536 float4 slots
    int idx = blockIdx.x * 256 + threadIdx.x;
    if (idx >= total4) return;
    const float4* p = reinterpret_cast<const float4*>(g_part);
    float4 s = p[idx];
    #pragma unroll
    for (int k = 1; k < KSPLIT; k++) {
        float4 v = p[(size_t)k * total4 + idx];
        s.x += v.x; s.y += v.y; s.z += v.z; s.w += v.w;
    }
    reinterpret_cast<float4*>(out)[idx] = s;
}

// ---------------------------------------------------------------------------
extern "C" void kernel_launch(void* const* d_in, const int* in_sizes, int n_in,
                              void* d_out, int out_size)
{
    const float* feature = (const float*)d_in[0];
    const float* coords  = (const float*)d_in[1];
    if (n_in >= 2 && in_sizes[0] == B_ * M_ * P_ * 2) {
        feature = (const float*)d_in[1];
        coords  = (const float*)d_in[0];
    }

    cudaFuncSetAttribute(pass2_mma, cudaFuncAttributeMaxDynamicSharedMemorySize, SMEM_TOTAL);

    pass1_weights<<<B_ * M_, 256>>>(coords);

    dim3 g2(NBLKS, B_, KSPLIT);
    pass2_mma<<<g2, 256, SMEM_TOTAL>>>(feature);

    const int total4 = B_ * M_ * C_ / 4;            // 65536
    pass3_reduce<<<(total4 + 255) / 256, 256>>>((float*)d_out);
}